// round 5
// baseline (speedup 1.0000x reference)
#include <cuda_runtime.h>
#include <cstdint>

#define BB 256   // batch
#define DD 256   // groups
#define KK 1024  // codes
#define EE 16    // embed dim
#define DECAY 0.999f
#define GAINF 0.001f
#define EPSF 1e-6f

#define NS  2           // K halves, one block each
#define KH  (KK / NS)   // 512 codes per block
#define NT1 512
#define NQ  2           // in-block K splits
#define KPT (KH / NQ)   // 256 codes per thread

typedef unsigned long long u64;

__device__ __forceinline__ u64 fma2(u64 a, u64 b, u64 c) {
    u64 d; asm("fma.rn.f32x2 %0, %1, %2, %3;" : "=l"(d) : "l"(a), "l"(b), "l"(c));
    return d;
}
__device__ __forceinline__ u64 mul2(u64 a, u64 b) {
    u64 d; asm("mul.rn.f32x2 %0, %1, %2;" : "=l"(d) : "l"(a), "l"(b));
    return d;
}
__device__ __forceinline__ u64 add2(u64 a, u64 b) {
    u64 d; asm("add.rn.f32x2 %0, %1, %2;" : "=l"(d) : "l"(a), "l"(b));
    return d;
}
__device__ __forceinline__ float2 upk(u64 v) {
    float2 r; asm("mov.b64 {%0, %1}, %2;" : "=f"(r.x), "=f"(r.y) : "l"(v));
    return r;
}

// partial results: packed (dist_bits<<32 | global_k) per (d, b, half)
__device__ u64 g_scratch[(size_t)DD * BB * NS];

// k1 smem (floats): cb 8192 | c2h 512 | red_d 512 | red_i 512 | zbuf 1024 = 10752 (42 KB)
#define SM1_FLOATS (KH*EE + KH + NQ*BB + NQ*BB + KK)

__global__ __launch_bounds__(NT1, 2)
void vq_k1(const float* __restrict__ cw_q,      // [B, D*E]
           const float* __restrict__ codebook,  // [D, K, E]
           const float* __restrict__ ema,       // [D, K]
           float* __restrict__ out_onehot,      // [B, D, K]
           float* __restrict__ out_cb,          // [D, K, E]
           float* __restrict__ out_ema)         // [D, K]
{
    const int d   = blockIdx.x >> 1;
    const int h   = blockIdx.x & 1;
    const int tid = threadIdx.x;

    extern __shared__ float sm[];
    float* cb_s  = sm;                      // KH*EE
    float* c2_s  = cb_s + KH*EE;            // KH   (0.5*||c||^2)
    float* red_d = c2_s + KH;               // NQ*BB
    int*   red_i = (int*)(red_d + NQ*BB);   // NQ*BB
    float* zbuf  = (float*)(red_i + NQ*BB); // KK zeros (one one_hot row)

    // ---- Phase 0: codebook half -> smem; out_cb decay base; zbuf; ema base ----
    {
        const float4* cbg = (const float4*)(codebook + (size_t)d * KK * EE
                                                     + (size_t)h * KH * EE);
        float4* ob4 = (float4*)(out_cb + (size_t)d * KK * EE + (size_t)h * KH * EE);
        float4* cb4 = (float4*)cb_s;
        #pragma unroll
        for (int i = tid; i < KH*EE/4; i += NT1) {
            float4 v = cbg[i];
            cb4[i] = v;
            ob4[i] = make_float4(v.x*DECAY, v.y*DECAY, v.z*DECAY, v.w*DECAY);
        }
        for (int i = tid; i < KK; i += NT1) zbuf[i] = 0.0f;
        if (h == 0) {
            const float* eg = ema + (size_t)d * KK;
            float*       oe = out_ema + (size_t)d * KK;
            for (int k = tid; k < KK; k += NT1) oe[k] = DECAY * eg[k];
        }
    }
    __syncthreads();
    // generic->async proxy ordering before TMA reads zbuf
    asm volatile("fence.proxy.async.shared::cta;" ::: "memory");

    // ---- one_hot zero rows via bulk async store (TMA pipe, off the LSU) ----
    if (tid < BB/NS) {
        const int bb = h * (BB/NS) + tid;
        float* grow = out_onehot + (size_t)bb * (DD*KK) + (size_t)d * KK;
        uint32_t zs = (uint32_t)__cvta_generic_to_shared(zbuf);
        asm volatile("cp.async.bulk.global.shared::cta.bulk_group [%0], [%1], %2;"
                     :: "l"(grow), "r"(zs), "r"(KK*4) : "memory");
        asm volatile("cp.async.bulk.commit_group;" ::: "memory");
    }

    // ---- Phase 1: c2h[k] = 0.5*||c_k||^2 ----
    #pragma unroll
    for (int k = tid; k < KH; k += NT1) {
        const float4* row = (const float4*)(cb_s + k*EE);
        float s = 0.0f;
        #pragma unroll
        for (int i = 0; i < EE/4; i++) {
            float4 v = row[i];
            s = fmaf(v.x, v.x, s); s = fmaf(v.y, v.y, s);
            s = fmaf(v.z, v.z, s); s = fmaf(v.w, v.w, s);
        }
        c2_s[k] = 0.5f * s;
    }
    __syncthreads();

    // ---- Phase 2: argmin. thread (b = tid&255, q = tid>>8), 1 row, KPT codes ----
    const int b  = tid & 255;
    const int q  = tid >> 8;
    const int k0 = q * KPT;

    u64 xp[EE/2];
    {
        const ulonglong2* xg = (const ulonglong2*)(cw_q
                              + (size_t)b * (DD*EE) + (size_t)d * EE);
        #pragma unroll
        for (int i = 0; i < 4; i++) {
            ulonglong2 v = xg[i];
            xp[2*i]   = v.x;
            xp[2*i+1] = v.y;
        }
    }

    float best = __int_as_float(0x7f800000);
    int   bi   = k0;
    const ulonglong2* cbp = (const ulonglong2*)cb_s;
    #pragma unroll 2
    for (int k = k0; k < k0 + KPT; k++) {
        ulonglong2 p0 = cbp[k*4+0];
        ulonglong2 p1 = cbp[k*4+1];
        ulonglong2 p2 = cbp[k*4+2];
        ulonglong2 p3 = cbp[k*4+3];
        u64 a0 = mul2(xp[0], p0.x);
        u64 a1 = mul2(xp[4], p2.x);
        a0 = fma2(xp[1], p0.y, a0);
        a1 = fma2(xp[5], p2.y, a1);
        a0 = fma2(xp[2], p1.x, a0);
        a1 = fma2(xp[6], p3.x, a1);
        a0 = fma2(xp[3], p1.y, a0);
        a1 = fma2(xp[7], p3.y, a1);
        float2 s = upk(add2(a0, a1));
        float dist = c2_s[k] - (s.x + s.y);   // x^2 dropped: argmin-invariant
        if (dist < best) { best = dist; bi = k; }
    }
    red_d[q*BB + b] = best;
    red_i[q*BB + b] = bi;
    __syncthreads();

    // ---- combine q-splits (ascending q => first-min ties), write scratch ----
    if (tid < BB) {
        float fb = red_d[tid];
        int   fi = red_i[tid];
        float d1 = red_d[BB + tid];
        if (d1 < fb) { fb = d1; fi = red_i[BB + tid]; }
        g_scratch[((size_t)d * BB + tid) * NS + h] =
            ((u64)(uint32_t)__float_as_uint(fb) << 32) | (uint32_t)(fi + h*KH);
    }

    if (tid < BB/NS)
        asm volatile("cp.async.bulk.wait_group 0;" ::: "memory");
}

// ---- kernel 2: per-(d,b) final combine + epilogue, no smem ----
__global__ __launch_bounds__(256)
void vq_k2(const float* __restrict__ cw_q,
           const float* __restrict__ codebook,
           const float* __restrict__ ema,
           float* __restrict__ out_embed,
           float* __restrict__ out_onehot,
           float* __restrict__ out_cb,
           float* __restrict__ out_ema)
{
    const int d = blockIdx.x;
    const int b = threadIdx.x;

    const u64* sp = &g_scratch[((size_t)d * BB + b) * NS];
    u64 p0 = sp[0];
    u64 p1 = sp[1];
    float f0 = __uint_as_float((uint32_t)(p0 >> 32));
    float f1 = __uint_as_float((uint32_t)(p1 >> 32));
    int   fi = (f1 < f0) ? (int)(uint32_t)(p1 & 0xffffffffu)
                         : (int)(uint32_t)(p0 & 0xffffffffu);

    // cw_embed[b, d] = codebook[d, fi]  (gather from L2-hot codebook)
    {
        const float4* src = (const float4*)(codebook + (size_t)d * KK * EE
                                                     + (size_t)fi * EE);
        float4* eo = (float4*)(out_embed + (size_t)b * (DD*EE) + (size_t)d * EE);
        #pragma unroll
        for (int i = 0; i < EE/4; i++) eo[i] = src[i];
    }
    // one_hot '1' (zeros written by k1, ordered by kernel boundary)
    out_onehot[(size_t)b * (DD*KK) + (size_t)d * KK + fi] = 1.0f;

    // EMA updates (bases DECAY*cb, DECAY*ema written by k1)
    const float em  = ema[(size_t)d * KK + fi];
    const float den = GAINF / (em + EPSF);
    const float* xb = cw_q + (size_t)b * (DD*EE) + (size_t)d * EE;
    float* dst = out_cb + (size_t)d * KK * EE + (size_t)fi * EE;
    #pragma unroll
    for (int e = 0; e < EE; e++)
        atomicAdd(&dst[e], den * xb[e]);
    atomicAdd(&out_ema[(size_t)d * KK + fi], GAINF);
}

extern "C" void kernel_launch(void* const* d_in, const int* in_sizes, int n_in,
                              void* d_out, int out_size)
{
    const float* cw_q     = (const float*)d_in[0];
    const float* codebook = (const float*)d_in[1];
    const float* ema      = (const float*)d_in[2];

    float* out        = (float*)d_out;
    float* out_embed  = out;                                   // B*D*E
    float* out_onehot = out_embed  + (size_t)BB * DD * EE;     // B*D*K
    float* out_cb     = out_onehot + (size_t)BB * DD * KK;     // D*K*E
    float* out_ema    = out_cb     + (size_t)DD * KK * EE;     // D*K

    const size_t sm1 = (size_t)SM1_FLOATS * sizeof(float);
    cudaFuncSetAttribute(vq_k1, cudaFuncAttributeMaxDynamicSharedMemorySize, (int)sm1);

    vq_k1<<<DD * NS, NT1, sm1>>>(cw_q, codebook, ema, out_onehot, out_cb, out_ema);
    vq_k2<<<DD, 256>>>(cw_q, codebook, ema, out_embed, out_onehot, out_cb, out_ema);
}

// round 8
// speedup vs baseline: 1.1399x; 1.1399x over previous
#include <cuda_runtime.h>
#include <cstdint>

#define BB 256   // batch
#define DD 256   // groups
#define KK 1024  // codes
#define EE 16    // embed dim
#define DECAY 0.999f
#define GAINF 0.001f
#define EPSF 1e-6f

#define NS  2           // K halves, one block each
#define KH  (KK / NS)   // 512 codes per block
#define NT1 512
#define NQ  4           // in-block K splits
#define KPT (KH / NQ)   // 128 codes per thread
#define BPT 2           // batch rows per thread

typedef unsigned long long u64;

__device__ __forceinline__ u64 fma2(u64 a, u64 b, u64 c) {
    u64 d; asm("fma.rn.f32x2 %0, %1, %2, %3;" : "=l"(d) : "l"(a), "l"(b), "l"(c));
    return d;
}
__device__ __forceinline__ u64 mul2(u64 a, u64 b) {
    u64 d; asm("mul.rn.f32x2 %0, %1, %2;" : "=l"(d) : "l"(a), "l"(b));
    return d;
}
__device__ __forceinline__ float2 upk(u64 v) {
    float2 r; asm("mov.b64 {%0, %1}, %2;" : "=f"(r.x), "=f"(r.y) : "l"(v));
    return r;
}

// partial results: packed (dist_bits<<32 | global_k) per (d, b, half)
__device__ u64 g_scratch[(size_t)DD * BB * NS];

// k1 smem (floats): cb 8192 | c2h 512 | red_d 1024 | red_i 1024 | zbuf 1024 = 11776 (46 KB)
#define SM1_FLOATS (KH*EE + KH + NQ*BB + NQ*BB + KK)

__global__ __launch_bounds__(NT1, 2)
void vq_k1(const float* __restrict__ cw_q,      // [B, D*E]
           const float* __restrict__ codebook,  // [D, K, E]
           const float* __restrict__ ema,       // [D, K]
           float* __restrict__ out_onehot,      // [B, D, K]
           float* __restrict__ out_cb,          // [D, K, E]
           float* __restrict__ out_ema)         // [D, K]
{
    const int d   = blockIdx.x >> 1;
    const int h   = blockIdx.x & 1;
    const int tid = threadIdx.x;

    extern __shared__ float sm[];
    float* cb_s  = sm;                      // KH*EE
    float* c2_s  = cb_s + KH*EE;            // KH   (0.5*||c||^2)
    float* red_d = c2_s + KH;               // NQ*BB
    int*   red_i = (int*)(red_d + NQ*BB);   // NQ*BB
    float* zbuf  = (float*)(red_i + NQ*BB); // KK zeros (one one_hot row)

    // ---- prefetch this thread's 2 x-rows EARLY (overlaps all smem phases) ----
    const int b0 = (tid & 127) * BPT;
    const int q  = tid >> 7;              // 0..3
    u64 xp0[EE/2], xp1[EE/2];
    {
        const ulonglong2* xg0 = (const ulonglong2*)(cw_q
                               + (size_t)b0 * (DD*EE) + (size_t)d * EE);
        const ulonglong2* xg1 = (const ulonglong2*)(cw_q
                               + (size_t)(b0+1) * (DD*EE) + (size_t)d * EE);
        #pragma unroll
        for (int i = 0; i < 4; i++) {
            ulonglong2 v0 = xg0[i];
            ulonglong2 v1 = xg1[i];
            xp0[2*i] = v0.x; xp0[2*i+1] = v0.y;
            xp1[2*i] = v1.x; xp1[2*i+1] = v1.y;
        }
    }

    // ---- Phase 0: codebook half -> smem; out_cb decay base; zbuf; ema base ----
    {
        const float4* cbg = (const float4*)(codebook + (size_t)d * KK * EE
                                                     + (size_t)h * KH * EE);
        float4* ob4 = (float4*)(out_cb + (size_t)d * KK * EE + (size_t)h * KH * EE);
        float4* cb4 = (float4*)cb_s;
        #pragma unroll
        for (int i = tid; i < KH*EE/4; i += NT1) {
            float4 v = cbg[i];
            cb4[i] = v;
            ob4[i] = make_float4(v.x*DECAY, v.y*DECAY, v.z*DECAY, v.w*DECAY);
        }
        for (int i = tid; i < KK; i += NT1) zbuf[i] = 0.0f;
        if (h == 0) {
            const float* eg = ema + (size_t)d * KK;
            float*       oe = out_ema + (size_t)d * KK;
            for (int k = tid; k < KK; k += NT1) oe[k] = DECAY * eg[k];
        }
    }
    __syncthreads();
    // generic->async proxy ordering before TMA reads zbuf
    asm volatile("fence.proxy.async.shared::cta;" ::: "memory");

    // ---- one_hot zero rows via bulk async store (TMA pipe, off the LSU) ----
    if (tid < BB/NS) {
        const int bb = h * (BB/NS) + tid;
        float* grow = out_onehot + (size_t)bb * (DD*KK) + (size_t)d * KK;
        uint32_t zs = (uint32_t)__cvta_generic_to_shared(zbuf);
        asm volatile("cp.async.bulk.global.shared::cta.bulk_group [%0], [%1], %2;"
                     :: "l"(grow), "r"(zs), "r"(KK*4) : "memory");
        asm volatile("cp.async.bulk.commit_group;" ::: "memory");
    }

    // ---- Phase 1: c2h[k] = 0.5*||c_k||^2 ----
    #pragma unroll
    for (int k = tid; k < KH; k += NT1) {
        const float4* row = (const float4*)(cb_s + k*EE);
        float s = 0.0f;
        #pragma unroll
        for (int i = 0; i < EE/4; i++) {
            float4 v = row[i];
            s = fmaf(v.x, v.x, s); s = fmaf(v.y, v.y, s);
            s = fmaf(v.z, v.z, s); s = fmaf(v.w, v.w, s);
        }
        c2_s[k] = 0.5f * s;
    }
    __syncthreads();

    // ---- Phase 2: argmin; 2 rows per thread, KPT codes, LDS amortized 2x ----
    const int k0 = q * KPT;
    float best0 = __int_as_float(0x7f800000);
    float best1 = __int_as_float(0x7f800000);
    int   bi0 = k0, bi1 = k0;

    const ulonglong2* cbp = (const ulonglong2*)cb_s;
    #pragma unroll 2
    for (int k = k0; k < k0 + KPT; k++) {
        // first half of the code row
        ulonglong2 p0 = cbp[k*4+0];
        ulonglong2 p1 = cbp[k*4+1];
        u64 a0 = mul2(xp0[0], p0.x);
        u64 a1 = mul2(xp1[0], p0.x);
        a0 = fma2(xp0[1], p0.y, a0);
        a1 = fma2(xp1[1], p0.y, a1);
        a0 = fma2(xp0[2], p1.x, a0);
        a1 = fma2(xp1[2], p1.x, a1);
        a0 = fma2(xp0[3], p1.y, a0);
        a1 = fma2(xp1[3], p1.y, a1);
        // second half
        ulonglong2 p2 = cbp[k*4+2];
        ulonglong2 p3 = cbp[k*4+3];
        a0 = fma2(xp0[4], p2.x, a0);
        a1 = fma2(xp1[4], p2.x, a1);
        a0 = fma2(xp0[5], p2.y, a0);
        a1 = fma2(xp1[5], p2.y, a1);
        a0 = fma2(xp0[6], p3.x, a0);
        a1 = fma2(xp1[6], p3.x, a1);
        a0 = fma2(xp0[7], p3.y, a0);
        a1 = fma2(xp1[7], p3.y, a1);

        float c2k = c2_s[k];
        float2 s0 = upk(a0);
        float2 s1 = upk(a1);
        float d0 = c2k - (s0.x + s0.y);   // x^2 dropped: argmin-invariant
        float d1 = c2k - (s1.x + s1.y);
        if (d0 < best0) { best0 = d0; bi0 = k; }
        if (d1 < best1) { best1 = d1; bi1 = k; }
    }
    red_d[q*BB + b0]     = best0;
    red_i[q*BB + b0]     = bi0;
    red_d[q*BB + b0 + 1] = best1;
    red_i[q*BB + b0 + 1] = bi1;
    __syncthreads();

    // ---- combine q-splits (ascending q => first-min ties), write scratch ----
    if (tid < BB) {
        float fb = red_d[tid];
        int   fi = red_i[tid];
        #pragma unroll
        for (int qq = 1; qq < NQ; qq++) {
            float dq = red_d[qq*BB + tid];
            if (dq < fb) { fb = dq; fi = red_i[qq*BB + tid]; }
        }
        g_scratch[((size_t)d * BB + tid) * NS + h] =
            ((u64)(uint32_t)__float_as_uint(fb) << 32) | (uint32_t)(fi + h*KH);
    }

    if (tid < BB/NS)
        asm volatile("cp.async.bulk.wait_group 0;" ::: "memory");
}

// ---- kernel 2: per-(d,b) combine + epilogue; 512 small blocks = 1 wave ----
__global__ __launch_bounds__(128)
void vq_k2(const float* __restrict__ cw_q,
           const float* __restrict__ codebook,
           const float* __restrict__ ema,
           float* __restrict__ out_embed,
           float* __restrict__ out_onehot,
           float* __restrict__ out_cb,
           float* __restrict__ out_ema)
{
    const int d = blockIdx.x >> 1;
    const int b = ((blockIdx.x & 1) << 7) | threadIdx.x;

    // both halves' packed (dist|k) in one 16-byte load
    ulonglong2 p = *(const ulonglong2*)&g_scratch[((size_t)d * BB + b) * NS];
    float f0 = __uint_as_float((uint32_t)(p.x >> 32));
    float f1 = __uint_as_float((uint32_t)(p.y >> 32));
    int   fi = (f1 < f0) ? (int)(uint32_t)(p.y & 0xffffffffu)
                         : (int)(uint32_t)(p.x & 0xffffffffu);

    // cw_embed[b, d] = codebook[d, fi]
    {
        const float4* src = (const float4*)(codebook + (size_t)d * KK * EE
                                                     + (size_t)fi * EE);
        float4 v0 = src[0], v1 = src[1], v2 = src[2], v3 = src[3];
        float4* eo = (float4*)(out_embed + (size_t)b * (DD*EE) + (size_t)d * EE);
        eo[0] = v0; eo[1] = v1; eo[2] = v2; eo[3] = v3;
    }
    // one_hot '1' (zeros written+drained by k1; ordered by kernel boundary)
    out_onehot[(size_t)b * (DD*KK) + (size_t)d * KK + fi] = 1.0f;

    // EMA updates (bases DECAY*cb, DECAY*ema written by k1)
    const float em  = ema[(size_t)d * KK + fi];
    const float den = GAINF / (em + EPSF);
    const float* xb = cw_q + (size_t)b * (DD*EE) + (size_t)d * EE;
    float* dst = out_cb + (size_t)d * KK * EE + (size_t)fi * EE;
    #pragma unroll
    for (int e = 0; e < EE; e++)
        atomicAdd(&dst[e], den * xb[e]);
    atomicAdd(&out_ema[(size_t)d * KK + fi], GAINF);
}

extern "C" void kernel_launch(void* const* d_in, const int* in_sizes, int n_in,
                              void* d_out, int out_size)
{
    const float* cw_q     = (const float*)d_in[0];
    const float* codebook = (const float*)d_in[1];
    const float* ema      = (const float*)d_in[2];

    float* out        = (float*)d_out;
    float* out_embed  = out;                                   // B*D*E
    float* out_onehot = out_embed  + (size_t)BB * DD * EE;     // B*D*K
    float* out_cb     = out_onehot + (size_t)BB * DD * KK;     // D*K*E
    float* out_ema    = out_cb     + (size_t)DD * KK * EE;     // D*K

    const size_t sm1 = (size_t)SM1_FLOATS * sizeof(float);
    cudaFuncSetAttribute(vq_k1, cudaFuncAttributeMaxDynamicSharedMemorySize, (int)sm1);

    vq_k1<<<DD * NS, NT1, sm1>>>(cw_q, codebook, ema, out_onehot, out_cb, out_ema);
    vq_k2<<<DD * 2, 128>>>(cw_q, codebook, ema, out_embed, out_onehot, out_cb, out_ema);
}